// round 13
// baseline (speedup 1.0000x reference)
#include <cuda_runtime.h>

// ARIMA(16,1,16), S = 2^20 — recurrence-free: err[t] = sum_{i<=80} hh[i]*s[t+1-i],
// hh = g (x) q (g = 64-tap MA impulse response, q = 18-tap diff+AR FIR).
// One kernel, 128 blocks x 512 threads (16 warps/block = 4 per SMSP for
// latency hiding). Per block: packed-pair smem ps[u] = (s[u], s[u+1])
// (64-bit, pad u+(u>>4)); lane0 generates g under the build. Conv: each lane
// computes 16 outputs = 8 f32x2 pairs via rolling 16-ull register window,
// static modular indexing: per tap 8 fma2 + 1 LDS.64 + 1 broadcast LDS.64.
// Outputs t<96 masked and computed exactly. Last-block reduction in-kernel.

#define S_LEN 1048576
#define WPB   16
#define NBLK  128
#define NWARP (NBLK * WPB)         // 2048
#define OPB   8192                 // outputs per block (16 warps x 512)
#define NPS   8276                 // ps pairs built per block
#define PSALLOC 8800               // padded ull allocation
#define PF(u) ((u) + ((u) >> 4))

typedef unsigned long long ull;

__device__ float    g_partial[NWARP];
__device__ unsigned g_cnt;          // zero-init; reset by last block

__device__ __forceinline__ ull pack2(float lo, float hi) {
    ull r; asm("mov.b64 %0, {%1,%2};" : "=l"(r) : "f"(lo), "f"(hi)); return r;
}
__device__ __forceinline__ void unpack2(ull v, float& lo, float& hi) {
    asm("mov.b64 {%0,%1}, %2;" : "=f"(lo), "=f"(hi) : "l"(v));
}
__device__ __forceinline__ ull fma2(ull a, ull b, ull c) {
    ull r; asm("fma.rn.f32x2 %0, %1, %2, %3;" : "=l"(r)
               : "l"(a), "l"(b), "l"(c));
    return r;
}

// 2 recurrence steps emitting both outputs (only used to generate g).
__device__ __forceinline__ void step2g(ull* P, const ull* PA, const ull* PB,
                                       float nc0, float x0, float x1,
                                       float& e0, float& e1) {
    float d0, d1;
    unpack2(P[0], d0, d1);
    e0 = x0 + d0;
    e1 = fmaf(nc0, e0, x1 + d1);
    ull E = pack2(e0, e0), Fv = pack2(e1, e1);
#pragma unroll
    for (int k = 0; k < 8; ++k)
        P[k] = fma2(PB[k], Fv, fma2(PA[k], E, P[k + 1]));
}

__global__ void __launch_bounds__(512) fused_kernel(const float* __restrict__ s,
                                                    const float* __restrict__ w_ar,
                                                    const float* __restrict__ w_ma,
                                                    float* __restrict__ out) {
    extern __shared__ __align__(16) ull ps[];       // [PSALLOC]
    __shared__ float    garr[64];
    __shared__ ull      hh2s[81];
    __shared__ float    xs[96];
    __shared__ double   sm[WPB];
    __shared__ unsigned s_done;

    const int tid = threadIdx.x;
    const int l   = tid & 31;
    const int wid = tid >> 5;
    const int bid = blockIdx.x;
    const int gw  = bid * WPB + wid;
    const int bb  = bid * OPB;          // first output of this block
    const int SSB = bb - 80;            // ps[u] = (s[SSB+u], s[SSB+u+1])

    // ---- Phase 0: lane 0 of warp 0 generates g; tid>=32 builds ps ----
    if (wid == 0) {
        if (l == 0) {
            float nc[16];
#pragma unroll
            for (int j = 0; j < 16; ++j) nc[j] = -w_ma[15 - j];
            ull PA[8], PB[8];
#pragma unroll
            for (int k = 0; k < 8; ++k) {
                PA[k] = pack2(nc[2 * k + 1],
                              (2 * k + 2 < 16) ? nc[2 * k + 2] : 0.f);
                PB[k] = pack2(nc[2 * k], nc[2 * k + 1]);
            }
            ull P[9];
#pragma unroll
            for (int k = 0; k < 9; ++k) P[k] = 0ULL;
            for (int it = 0; it < 32; ++it) {
                float e0, e1;
                step2g(P, PA, PB, nc[0], (it == 0) ? 1.f : 0.f, 0.f, e0, e1);
                garr[2 * it]     = e0;
                garr[2 * it + 1] = e1;
            }
        }
    } else {
        const int i0 = tid - 32;        // 480 builder threads
        if (bid == 0 || bid == NBLK - 1) {
            for (int u = i0; u < NPS; u += 480) {
                int p0 = SSB + u, p1 = SSB + u + 1;
                p0 = p0 < 0 ? 0 : (p0 > S_LEN ? S_LEN : p0);
                p1 = p1 < 0 ? 0 : (p1 > S_LEN ? S_LEN : p1);
                ps[PF(u)] = pack2(s[p0], s[p1]);
            }
        } else {
            const float4* src = (const float4*)(s + SSB);   // SSB % 4 == 0
            const float*  sf  = s + SSB;
            for (int i = i0; i < 2069; i += 480) {          // covers u<8276
                float4 a = src[i];
                float  nx = sf[4 * i + 4];
                const int u = 4 * i;
                ps[PF(u)]     = pack2(a.x, a.y);
                ps[PF(u + 1)] = pack2(a.y, a.z);
                ps[PF(u + 2)] = pack2(a.z, a.w);
                ps[PF(u + 3)] = pack2(a.w, nx);
            }
        }
    }
    __syncthreads();

    // ---- Phase 1: hh = g (x) q (81 taps); block 0 builds x~[0..95] ----
    if (tid < 81) {
        float q[18];
        q[0] = w_ar[0];
#pragma unroll
        for (int m = 1; m < 16; ++m) q[m] = w_ar[m] - w_ar[m - 1];
        q[16] = -1.f - w_ar[15];
        q[17] = 1.f;
        float h = 0.f;
#pragma unroll
        for (int m = 0; m < 18; ++m) {
            int k = tid - 17 + m;       // hh[i] = sum_k g[k] q[k+17-i]
            if (k >= 0 && k < 64) h = fmaf(q[m], garr[k], h);
        }
        hh2s[tid] = pack2(h, h);
    }
    if (bid == 0 && tid >= 160 && tid < 256) {
        const int u = tid - 160;        // 0..95
        float v;
        if (u <= 16) {                  // x~ = y_u + sum_{j<=u} c_j y_{u-j}
            v = s[u + 1] - s[u];
            for (int j = 1; j <= u; ++j)
                v = fmaf(w_ma[16 - j], s[u - j + 1] - s[u - j], v);
        } else {                        // x = 18-tap q conv on s[u-16..u+1]
            float q[18];
            q[0] = w_ar[0];
#pragma unroll
            for (int m = 1; m < 16; ++m) q[m] = w_ar[m] - w_ar[m - 1];
            q[16] = -1.f - w_ar[15];
            q[17] = 1.f;
            v = 0.f;
#pragma unroll
            for (int m = 0; m < 18; ++m)
                v = fmaf(q[m], s[u - 16 + m], v);
        }
        xs[u] = v;
    }
    __syncthreads();

    // ---- Phase 2a: block 0 warp 0 — exact err for t in [0, 96) ----
    float accE = 0.f;
    if (bid == 0 && wid == 0) {
#pragma unroll
        for (int rr = 0; rr < 3; ++rr) {
            int t = l + 32 * rr;        // < 96
            float e = 0.f;
            int kmax = t < 63 ? t : 63;
            for (int k = 0; k <= kmax; ++k)
                e = fmaf(garr[k], xs[t - k], e);
            accE = fmaf(e, e, accE);
        }
    }

    // ---- Phase 2b: 81-tap packed conv, 16 outputs (8 pairs) per lane ----
    // Window invariant at tap T: W[(T+m)&15] = ps[tloc+1+T+m], m=0..15.
    // Pair p uses m = 2p; refill after tap T: W[T&15] = ps[tloc+T+17].
    const int tloc = wid * 512 + 16 * l;      // block-local first output
    ull E[8];
#pragma unroll
    for (int p = 0; p < 8; ++p) E[p] = 0ULL;
    ull W[16];
#pragma unroll
    for (int m = 0; m < 16; ++m) W[m] = ps[PF(tloc + 1 + m)];

#pragma unroll 1
    for (int o = 0; o < 5; ++o) {             // taps 0..79
        const int Tb = 16 * o;
#pragma unroll
        for (int k = 0; k < 16; ++k) {
            ull h2 = hh2s[80 - (Tb + k)];
#pragma unroll
            for (int p = 0; p < 8; ++p)
                E[p] = fma2(h2, W[(k + 2 * p) & 15], E[p]);
            W[k] = ps[PF(tloc + Tb + k + 17)];
        }
    }
    {                                         // final tap T = 80 (80&15 = 0)
        ull h2 = hh2s[0];
#pragma unroll
        for (int p = 0; p < 8; ++p)
            E[p] = fma2(h2, W[(2 * p) & 15], E[p]);
    }

    ull acc2 = 0ULL;
    const bool skip = (gw == 0) & (l < 6);    // t < 96 handled exactly
    if (!skip) {
#pragma unroll
        for (int p = 0; p < 8; ++p)
            acc2 = fma2(E[p], E[p], acc2);
    }

    float alo, ahi;
    unpack2(acc2, alo, ahi);
    float acc = alo + ahi + accE;
#pragma unroll
    for (int off = 16; off; off >>= 1)
        acc += __shfl_down_sync(0xffffffffu, acc, off);
    if (l == 0) g_partial[gw] = acc;

    // ---- last-block-done final reduction ----
    __threadfence();
    __syncthreads();
    if (tid == 0) {
        unsigned old = atomicAdd(&g_cnt, 1u);
        s_done = (old == gridDim.x - 1) ? 1u : 0u;
    }
    __syncthreads();
    if (s_done) {
        double v = 0.0;
#pragma unroll
        for (int k = 0; k < NWARP / 512; ++k)
            v += (double)((volatile float*)g_partial)[tid + 512 * k];
#pragma unroll
        for (int off = 16; off; off >>= 1)
            v += __shfl_down_sync(0xffffffffu, v, off);
        if (l == 0) sm[wid] = v;
        __syncthreads();
        if (tid == 0) {
            double w = 0.0;
#pragma unroll
            for (int k = 0; k < WPB; ++k) w += sm[k];
            out[0] = (float)(w * (1.0 / (double)S_LEN));
            g_cnt = 0;                  // reset for next graph replay
        }
    }
}

extern "C" void kernel_launch(void* const* d_in, const int* in_sizes, int n_in,
                              void* d_out, int out_size) {
    const float* series = (const float*)d_in[0];
    const float* w_ar   = (const float*)d_in[1];
    const float* w_ma   = (const float*)d_in[2];
    float* out = (float*)d_out;
    cudaFuncSetAttribute(fused_kernel,
                         cudaFuncAttributeMaxDynamicSharedMemorySize,
                         PSALLOC * (int)sizeof(ull));
    fused_kernel<<<NBLK, 512, PSALLOC * sizeof(ull)>>>(series, w_ar, w_ma, out);
}

// round 17
// speedup vs baseline: 1.1186x; 1.1186x over previous
#include <cuda_runtime.h>

// ARIMA(16,1,16), S = 2^20 — recurrence-free: err[t] = sum_{i<=80} hh[i]*s[t+1-i],
// hh = g (x) q (g = 64-tap MA impulse response, q = 18-tap diff+AR FIR).
// 512 blocks x 128 threads (4 warps) — small co-resident blocks (~4-6/SM) so
// load/sync/tail phases of one block overlap another block's conv.
// Per block: packed-pair smem ps[u] = (s[u], s[u+1]) (64-bit, pad u+(u>>4));
// lane0 generates g under the build. Conv: each lane computes 16 outputs =
// 8 f32x2 pairs via rolling 16-ull register window, static modular indexing:
// per tap 8 fma2 + 1 LDS.64 + 1 broadcast LDS.64. Outputs t<96 masked and
// computed exactly. Last-block-done reduction in-kernel.
// R16 bugfix: builder quad-loop writes up to pair u=2131 (PF=2264), so
// PSALLOC must exceed 2264 — 2272 now (was 2264: the spill clobbered garr[0],
// i.e. g[0]=1.0, corrupting hh and every output).

#define S_LEN 1048576
#define WPB   4
#define NBLK  512
#define NWARP (NBLK * WPB)         // 2048
#define OPB   2048                 // outputs per block (4 warps x 512)
#define NPS   2129                 // ps pairs needed per block
#define PSALLOC 2272               // padded ull alloc; max write PF(2131)=2264
#define PF(u) ((u) + ((u) >> 4))

typedef unsigned long long ull;

__device__ float    g_partial[NWARP];
__device__ unsigned g_cnt;          // zero-init; reset by last block

__device__ __forceinline__ ull pack2(float lo, float hi) {
    ull r; asm("mov.b64 %0, {%1,%2};" : "=l"(r) : "f"(lo), "f"(hi)); return r;
}
__device__ __forceinline__ void unpack2(ull v, float& lo, float& hi) {
    asm("mov.b64 {%0,%1}, %2;" : "=f"(lo), "=f"(hi) : "l"(v));
}
__device__ __forceinline__ ull fma2(ull a, ull b, ull c) {
    ull r; asm("fma.rn.f32x2 %0, %1, %2, %3;" : "=l"(r)
               : "l"(a), "l"(b), "l"(c));
    return r;
}

// 2 recurrence steps emitting both outputs (only used to generate g).
__device__ __forceinline__ void step2g(ull* P, const ull* PA, const ull* PB,
                                       float nc0, float x0, float x1,
                                       float& e0, float& e1) {
    float d0, d1;
    unpack2(P[0], d0, d1);
    e0 = x0 + d0;
    e1 = fmaf(nc0, e0, x1 + d1);
    ull E = pack2(e0, e0), Fv = pack2(e1, e1);
#pragma unroll
    for (int k = 0; k < 8; ++k)
        P[k] = fma2(PB[k], Fv, fma2(PA[k], E, P[k + 1]));
}

__global__ void __launch_bounds__(128) fused_kernel(const float* __restrict__ s,
                                                    const float* __restrict__ w_ar,
                                                    const float* __restrict__ w_ma,
                                                    float* __restrict__ out) {
    __shared__ __align__(16) ull ps[PSALLOC];
    __shared__ float    garr[64];
    __shared__ ull      hh2s[81];
    __shared__ float    xs[96];
    __shared__ double   sm[WPB];
    __shared__ unsigned s_done;

    const int tid = threadIdx.x;
    const int l   = tid & 31;
    const int wid = tid >> 5;
    const int bid = blockIdx.x;
    const int gw  = bid * WPB + wid;
    const int bb  = bid * OPB;          // first output of this block
    const int SSB = bb - 80;            // ps[u] = (s[SSB+u], s[SSB+u+1])

    // ---- Phase 0: lane 0 of warp 0 generates g; tid>=32 builds ps ----
    if (wid == 0) {
        if (l == 0) {
            float nc[16];
#pragma unroll
            for (int j = 0; j < 16; ++j) nc[j] = -w_ma[15 - j];
            ull PA[8], PB[8];
#pragma unroll
            for (int k = 0; k < 8; ++k) {
                PA[k] = pack2(nc[2 * k + 1],
                              (2 * k + 2 < 16) ? nc[2 * k + 2] : 0.f);
                PB[k] = pack2(nc[2 * k], nc[2 * k + 1]);
            }
            ull P[9];
#pragma unroll
            for (int k = 0; k < 9; ++k) P[k] = 0ULL;
            for (int it = 0; it < 32; ++it) {
                float e0, e1;
                step2g(P, PA, PB, nc[0], (it == 0) ? 1.f : 0.f, 0.f, e0, e1);
                garr[2 * it]     = e0;
                garr[2 * it + 1] = e1;
            }
        }
    } else {
        const int i0 = tid - 32;        // 96 builder threads
        if (bid == 0 || bid == NBLK - 1) {
            for (int u = i0; u < NPS; u += 96) {
                int p0 = SSB + u, p1 = SSB + u + 1;
                p0 = p0 < 0 ? 0 : (p0 > S_LEN ? S_LEN : p0);
                p1 = p1 < 0 ? 0 : (p1 > S_LEN ? S_LEN : p1);
                ps[PF(u)] = pack2(s[p0], s[p1]);
            }
        } else {
            const float4* src = (const float4*)(s + SSB);   // SSB % 4 == 0
            const float*  sf  = s + SSB;
#pragma unroll 2
            for (int i = i0; i < 533; i += 96) {            // covers u<2129
                float4 a = src[i];
                float  nx = sf[4 * i + 4];
                const int u = 4 * i;
                ps[PF(u)]     = pack2(a.x, a.y);
                ps[PF(u + 1)] = pack2(a.y, a.z);
                ps[PF(u + 2)] = pack2(a.z, a.w);
                ps[PF(u + 3)] = pack2(a.w, nx);
            }
        }
    }
    __syncthreads();

    // ---- Phase 1: hh = g (x) q (81 taps); block 0 builds x~[0..95] ----
    if (tid < 81) {
        float q[18];
        q[0] = w_ar[0];
#pragma unroll
        for (int m = 1; m < 16; ++m) q[m] = w_ar[m] - w_ar[m - 1];
        q[16] = -1.f - w_ar[15];
        q[17] = 1.f;
        float h = 0.f;
#pragma unroll
        for (int m = 0; m < 18; ++m) {
            int k = tid - 17 + m;       // hh[i] = sum_k g[k] q[k+17-i]
            if (k >= 0 && k < 64) h = fmaf(q[m], garr[k], h);
        }
        hh2s[tid] = pack2(h, h);
    }
    if (bid == 0 && tid < 96) {
        const int u = tid;              // 0..95
        float v;
        if (u <= 16) {                  // x~ = y_u + sum_{j<=u} c_j y_{u-j}
            v = s[u + 1] - s[u];
            for (int j = 1; j <= u; ++j)
                v = fmaf(w_ma[16 - j], s[u - j + 1] - s[u - j], v);
        } else {                        // x = 18-tap q conv on s[u-16..u+1]
            float q[18];
            q[0] = w_ar[0];
#pragma unroll
            for (int m = 1; m < 16; ++m) q[m] = w_ar[m] - w_ar[m - 1];
            q[16] = -1.f - w_ar[15];
            q[17] = 1.f;
            v = 0.f;
#pragma unroll
            for (int m = 0; m < 18; ++m)
                v = fmaf(q[m], s[u - 16 + m], v);
        }
        xs[u] = v;
    }
    __syncthreads();

    // ---- Phase 2a: block 0 warp 0 — exact err for t in [0, 96) ----
    float accE = 0.f;
    if (bid == 0 && wid == 0) {
#pragma unroll
        for (int rr = 0; rr < 3; ++rr) {
            int t = l + 32 * rr;        // < 96
            float e = 0.f;
            int kmax = t < 63 ? t : 63;
            for (int k = 0; k <= kmax; ++k)
                e = fmaf(garr[k], xs[t - k], e);
            accE = fmaf(e, e, accE);
        }
    }

    // ---- Phase 2b: 81-tap packed conv, 16 outputs (8 pairs) per lane ----
    // Window invariant at tap T: W[(T+m)&15] = ps[tloc+1+T+m], m=0..15.
    // Pair p uses m = 2p; refill after tap T: W[T&15] = ps[tloc+T+17].
    const int tloc = wid * 512 + 16 * l;      // block-local first output
    ull E[8];
#pragma unroll
    for (int p = 0; p < 8; ++p) E[p] = 0ULL;
    ull W[16];
#pragma unroll
    for (int m = 0; m < 16; ++m) W[m] = ps[PF(tloc + 1 + m)];

#pragma unroll 1
    for (int o = 0; o < 5; ++o) {             // taps 0..79
        const int Tb = 16 * o;
#pragma unroll
        for (int k = 0; k < 16; ++k) {
            ull h2 = hh2s[80 - (Tb + k)];
#pragma unroll
            for (int p = 0; p < 8; ++p)
                E[p] = fma2(h2, W[(k + 2 * p) & 15], E[p]);
            W[k] = ps[PF(tloc + Tb + k + 17)];
        }
    }
    {                                         // final tap T = 80 (80&15 = 0)
        ull h2 = hh2s[0];
#pragma unroll
        for (int p = 0; p < 8; ++p)
            E[p] = fma2(h2, W[(2 * p) & 15], E[p]);
    }

    ull acc2 = 0ULL;
    const bool skip = (gw == 0) & (l < 6);    // t < 96 handled exactly
    if (!skip) {
#pragma unroll
        for (int p = 0; p < 8; ++p)
            acc2 = fma2(E[p], E[p], acc2);
    }

    float alo, ahi;
    unpack2(acc2, alo, ahi);
    float acc = alo + ahi + accE;
#pragma unroll
    for (int off = 16; off; off >>= 1)
        acc += __shfl_down_sync(0xffffffffu, acc, off);
    if (l == 0) g_partial[gw] = acc;

    // ---- last-block-done final reduction ----
    __threadfence();
    __syncthreads();
    if (tid == 0) {
        unsigned old = atomicAdd(&g_cnt, 1u);
        s_done = (old == gridDim.x - 1) ? 1u : 0u;
    }
    __syncthreads();
    if (s_done) {
        double v = 0.0;
#pragma unroll
        for (int k = 0; k < NWARP / 128; ++k)
            v += (double)((volatile float*)g_partial)[tid + 128 * k];
#pragma unroll
        for (int off = 16; off; off >>= 1)
            v += __shfl_down_sync(0xffffffffu, v, off);
        if (l == 0) sm[wid] = v;
        __syncthreads();
        if (tid == 0) {
            double w = sm[0] + sm[1] + sm[2] + sm[3];
            out[0] = (float)(w * (1.0 / (double)S_LEN));
            g_cnt = 0;                  // reset for next graph replay
        }
    }
}

extern "C" void kernel_launch(void* const* d_in, const int* in_sizes, int n_in,
                              void* d_out, int out_size) {
    const float* series = (const float*)d_in[0];
    const float* w_ar   = (const float*)d_in[1];
    const float* w_ma   = (const float*)d_in[2];
    float* out = (float*)d_out;
    fused_kernel<<<NBLK, 128>>>(series, w_ar, w_ma, out);
}